// round 1
// baseline (speedup 1.0000x reference)
#include <cuda_runtime.h>
#include <math.h>

// Problem constants (fixed by reference setup_inputs)
#define BB 32
#define SS 2048
#define DD 1024
#define NCHUNK 32
#define SC (SS / NCHUNK)        // 64 rows per block
#define TILE 8                  // rows per tile == warps per block
#define NTILE (SC / TILE)       // 8 tiles
#define THREADS 256
#define CPT (DD / THREADS)      // 4 columns per thread

#define NEG_BIG (-1e30f)

// Scratch for per-(batch,chunk) partials. Static device arrays (no alloc).
__device__ float g_acc[BB * NCHUNK * DD];   // 4 MB
__device__ float g_m[BB * NCHUNK];
__device__ float g_l[BB * NCHUNK];

// ---------------------------------------------------------------------------
// Kernel A: fused scores + online-softmax partial accumulation.
// Reads context exactly once from HBM. Writes raw masked scores into the
// attn region of d_out (rescaled to final softmax by kernel B).
// ---------------------------------------------------------------------------
__global__ __launch_bounds__(THREADS, 4)
void attn_partial_kernel(const float* __restrict__ h,
                         const float* __restrict__ context,
                         const int*   __restrict__ mask,
                         float* __restrict__ scores_out /* = d_out + BB*DD */)
{
    __shared__ float sh_h[DD];                 // 4 KB
    __shared__ float sh_tile[TILE][DD];        // 32 KB
    __shared__ float sh_scores[TILE];

    const int b     = blockIdx.y;
    const int chunk = blockIdx.x;
    const int tid   = threadIdx.x;
    const int warp  = tid >> 5;
    const int lane  = tid & 31;
    const int s0    = chunk * SC;

    // Stage h[b,:] into smem (float4, coalesced)
    {
        const float4* hv  = (const float4*)(h + (size_t)b * DD);
        float4*       shv = (float4*)sh_h;
        #pragma unroll
        for (int i = tid; i < DD / 4; i += THREADS) shv[i] = hv[i];
    }
    __syncthreads();

    float acc[CPT] = {0.f, 0.f, 0.f, 0.f};
    float m = NEG_BIG;
    float l = 0.f;

    for (int t = 0; t < NTILE; ++t) {
        const int s = s0 + t * TILE + warp;    // this warp's row

        // --- Phase 1: stream row -> smem, fused dot with h ---
        const float4* row  = (const float4*)(context + ((size_t)b * SS + s) * DD);
        float4*       srow = (float4*)sh_tile[warp];
        float dot = 0.f;
        #pragma unroll
        for (int i = 0; i < (DD / 4) / 32; ++i) {   // 8 iterations
            const int idx = lane + i * 32;
            float4 v = row[idx];                    // LDG.128, coalesced
            srow[idx] = v;                          // STS.128, conflict-free
            float4 hv = ((const float4*)sh_h)[idx];
            dot += v.x * hv.x + v.y * hv.y + v.z * hv.z + v.w * hv.w;
        }
        #pragma unroll
        for (int o = 16; o > 0; o >>= 1)
            dot += __shfl_xor_sync(0xffffffffu, dot, o);

        if (lane == 0) {
            const float sc = (mask[b * SS + s] == 0) ? NEG_BIG : dot;
            sh_scores[warp] = sc;
            scores_out[b * SS + s] = sc;            // raw masked score
        }
        __syncthreads();

        // --- Phase 2: online softmax accumulate from smem ---
        float tmax = NEG_BIG;
        #pragma unroll
        for (int r = 0; r < TILE; ++r) tmax = fmaxf(tmax, sh_scores[r]);
        const float new_m = fmaxf(m, tmax);
        const float scale = __expf(m - new_m);      // exp(0)=1 when both sentinel
        l *= scale;
        #pragma unroll
        for (int c = 0; c < CPT; ++c) acc[c] *= scale;

        float w[TILE];
        #pragma unroll
        for (int r = 0; r < TILE; ++r) {
            w[r] = __expf(sh_scores[r] - new_m);    // 0 for masked rows
            l += w[r];
        }
        m = new_m;

        #pragma unroll
        for (int r = 0; r < TILE; ++r) {
            float4 v = ((const float4*)sh_tile[r])[tid];   // LDS.128, conflict-free
            acc[0] += w[r] * v.x;
            acc[1] += w[r] * v.y;
            acc[2] += w[r] * v.z;
            acc[3] += w[r] * v.w;
        }
        __syncthreads();   // protect smem tile before next iteration overwrites
    }

    // Write partials (coalesced float4)
    const int pc = b * NCHUNK + chunk;
    ((float4*)(g_acc + (size_t)pc * DD))[tid] =
        make_float4(acc[0], acc[1], acc[2], acc[3]);
    if (tid == 0) { g_m[pc] = m; g_l[pc] = l; }
}

// ---------------------------------------------------------------------------
// Kernel B: combine partials -> weighted_context; rescale raw scores -> attn.
// out layout: [ weighted_context (BB*DD) | attn (BB*SS) ]
// ---------------------------------------------------------------------------
__global__ __launch_bounds__(256)
void attn_combine_kernel(float* __restrict__ out)
{
    const int b   = blockIdx.x;
    const int tid = threadIdx.x;

    __shared__ float sm[NCHUNK];
    __shared__ float sl[NCHUNK];
    if (tid < NCHUNK) {
        sm[tid] = g_m[b * NCHUNK + tid];
        sl[tid] = g_l[b * NCHUNK + tid];
    }
    __syncthreads();

    float M = NEG_BIG;
    #pragma unroll
    for (int c = 0; c < NCHUNK; ++c) M = fmaxf(M, sm[c]);

    float f[NCHUNK];
    float L = 0.f;
    #pragma unroll
    for (int c = 0; c < NCHUNK; ++c) {
        f[c] = __expf(sm[c] - M);   // kills fully-masked-chunk garbage (->0)
        L += sl[c] * f[c];
    }
    const float invL = 1.f / L;

    // weighted_context[b, :]
    #pragma unroll
    for (int d = tid; d < DD; d += 256) {
        float sum = 0.f;
        #pragma unroll
        for (int c = 0; c < NCHUNK; ++c)
            sum += g_acc[((size_t)(b * NCHUNK + c)) * DD + d] * f[c];
        out[(size_t)b * DD + d] = sum * invL;
    }

    // attn[b, :] : raw masked score -> softmax prob (in place)
    float* attn = out + (size_t)BB * DD;
    #pragma unroll
    for (int s = tid; s < SS; s += 256) {
        const float sc = attn[(size_t)b * SS + s];
        attn[(size_t)b * SS + s] = __expf(sc - M) * invL;
    }
}

// ---------------------------------------------------------------------------
extern "C" void kernel_launch(void* const* d_in, const int* in_sizes, int n_in,
                              void* d_out, int out_size)
{
    const float* h       = (const float*)d_in[0];
    const float* context = (const float*)d_in[1];
    const int*   mask    = (const int*)d_in[2];
    float*       out     = (float*)d_out;

    dim3 gridA(NCHUNK, BB);
    attn_partial_kernel<<<gridA, THREADS>>>(h, context, mask, out + BB * DD);
    attn_combine_kernel<<<BB, 256>>>(out);
}

// round 2
// speedup vs baseline: 1.1074x; 1.1074x over previous
#include <cuda_runtime.h>
#include <math.h>

// Problem constants (fixed by reference setup_inputs)
#define BB 32
#define SS 2048
#define DD 1024
#define NCHUNK 64
#define SC (SS / NCHUNK)        // 32 rows per block
#define TILE 8                  // rows per tile == warps per block
#define NTILE (SC / TILE)       // 4 tiles
#define THREADS 256
#define CPT (DD / THREADS)      // 4 columns per thread

#define NEG_BIG (-1e30f)

// Scratch for per-(batch,chunk) partials. Static device arrays (no alloc).
__device__ float g_acc[BB * NCHUNK * DD];   // 8 MB
__device__ float g_m[BB * NCHUNK];
__device__ float g_l[BB * NCHUNK];

// ---------------------------------------------------------------------------
// Kernel A: fused scores + online-softmax partial accumulation.
// Reads context exactly once from HBM. Register double-buffering: tile t+1's
// global loads are issued before phase-2 compute on tile t, so DRAM traffic
// overlaps the smem-resident accumulation.
// ---------------------------------------------------------------------------
__global__ __launch_bounds__(THREADS, 4)
void attn_partial_kernel(const float* __restrict__ h,
                         const float* __restrict__ context,
                         const int*   __restrict__ mask,
                         float* __restrict__ scores_out /* = d_out + BB*DD */)
{
    __shared__ float  sh_h[DD];                 // 4 KB
    __shared__ float4 sh_tile[TILE][DD / 4];    // 32 KB
    __shared__ float  sh_scores[TILE];

    const int b     = blockIdx.y;
    const int chunk = blockIdx.x;
    const int tid   = threadIdx.x;
    const int warp  = tid >> 5;
    const int lane  = tid & 31;
    const int s0    = chunk * SC;

    // Stage h[b,:] into smem (float4, coalesced)
    {
        const float4* hv  = (const float4*)(h + (size_t)b * DD);
        float4*       shv = (float4*)sh_h;
        #pragma unroll
        for (int i = tid; i < DD / 4; i += THREADS) shv[i] = hv[i];
    }
    __syncthreads();

    // Base row pointer for this warp (advances TILE rows per tile)
    const float4* rowp =
        (const float4*)(context + ((size_t)b * SS + s0 + warp) * DD);

    // Prefetch tile 0 into registers
    float4 r[8];
    #pragma unroll
    for (int i = 0; i < 8; ++i) r[i] = rowp[lane + i * 32];

    float acc[CPT] = {0.f, 0.f, 0.f, 0.f};
    float m = NEG_BIG;
    float l = 0.f;

    for (int t = 0; t < NTILE; ++t) {
        // --- Phase 1: regs -> smem, fused dot with h ---
        float dot = 0.f;
        #pragma unroll
        for (int i = 0; i < 8; ++i) {
            const int idx = lane + i * 32;
            sh_tile[warp][idx] = r[i];
            float4 hv = ((const float4*)sh_h)[idx];
            dot += r[i].x * hv.x + r[i].y * hv.y + r[i].z * hv.z + r[i].w * hv.w;
        }
        #pragma unroll
        for (int o = 16; o > 0; o >>= 1)
            dot += __shfl_xor_sync(0xffffffffu, dot, o);

        const int s = s0 + t * TILE + warp;
        if (lane == 0) {
            const float sc = (mask[b * SS + s] == 0) ? NEG_BIG : dot;
            sh_scores[warp] = sc;
            scores_out[b * SS + s] = sc;            // raw masked score
        }
        __syncthreads();

        // --- Prefetch tile t+1 (loads in flight during phase 2) ---
        if (t + 1 < NTILE) {
            const float4* nrow = rowp + (size_t)(t + 1) * TILE * (DD / 4);
            #pragma unroll
            for (int i = 0; i < 8; ++i) r[i] = nrow[lane + i * 32];
        }

        // --- Phase 2: online softmax accumulate from smem ---
        float tmax = NEG_BIG;
        #pragma unroll
        for (int rr = 0; rr < TILE; ++rr) tmax = fmaxf(tmax, sh_scores[rr]);
        const float new_m = fmaxf(m, tmax);
        const float scale = __expf(m - new_m);
        l *= scale;
        #pragma unroll
        for (int c = 0; c < CPT; ++c) acc[c] *= scale;

        float w[TILE];
        #pragma unroll
        for (int rr = 0; rr < TILE; ++rr) {
            w[rr] = __expf(sh_scores[rr] - new_m);  // 0 for masked rows
            l += w[rr];
        }
        m = new_m;

        #pragma unroll
        for (int rr = 0; rr < TILE; ++rr) {
            float4 v = sh_tile[rr][tid];            // LDS.128, conflict-free
            acc[0] += w[rr] * v.x;
            acc[1] += w[rr] * v.y;
            acc[2] += w[rr] * v.z;
            acc[3] += w[rr] * v.w;
        }
        __syncthreads();   // tile consumed; next iteration may overwrite
    }

    // Write partials (coalesced float4)
    const int pc = b * NCHUNK + chunk;
    ((float4*)(g_acc + (size_t)pc * DD))[tid] =
        make_float4(acc[0], acc[1], acc[2], acc[3]);
    if (tid == 0) { g_m[pc] = m; g_l[pc] = l; }
}

// ---------------------------------------------------------------------------
// Kernel B: combine partials. Parallelized: 3 blocks per batch.
//   part 0      : weighted_context[b,:]  (256 threads x float4 = 1024 cols)
//   part 1 & 2  : attn[b,:] rescale      (2 x 256 threads x float4 = 2048)
// out layout: [ weighted_context (BB*DD) | attn (BB*SS) ]
// ---------------------------------------------------------------------------
__global__ __launch_bounds__(256)
void attn_combine_kernel(float* __restrict__ out)
{
    const int part = blockIdx.x;   // 0..2
    const int b    = blockIdx.y;
    const int tid  = threadIdx.x;

    __shared__ float sm[NCHUNK];
    __shared__ float sl[NCHUNK];
    __shared__ float sw[NCHUNK];   // f[c] * invL
    if (tid < NCHUNK) {
        sm[tid] = g_m[b * NCHUNK + tid];
        sl[tid] = g_l[b * NCHUNK + tid];
    }
    __syncthreads();

    // Every thread redundantly computes M and L (cheap, no divergence)
    float M = NEG_BIG;
    #pragma unroll 8
    for (int c = 0; c < NCHUNK; ++c) M = fmaxf(M, sm[c]);
    float L = 0.f;
    #pragma unroll 8
    for (int c = 0; c < NCHUNK; ++c) L += sl[c] * __expf(sm[c] - M);
    const float invL = 1.f / L;

    if (part == 0) {
        if (tid < NCHUNK) sw[tid] = __expf(sm[tid] - M) * invL;
        __syncthreads();

        // weighted_context[b, :] : 1 float4 per thread, sum over 64 chunks
        float4 sum = make_float4(0.f, 0.f, 0.f, 0.f);
        const float4* accp = (const float4*)(g_acc + (size_t)b * NCHUNK * DD);
        #pragma unroll 8
        for (int c = 0; c < NCHUNK; ++c) {
            const float4 v = accp[(size_t)c * (DD / 4) + tid];
            const float  f = sw[c];
            sum.x += f * v.x; sum.y += f * v.y;
            sum.z += f * v.z; sum.w += f * v.w;
        }
        ((float4*)(out + (size_t)b * DD))[tid] = sum;
    } else {
        // attn[b, :] : raw masked score -> softmax prob (in place)
        float4* attn = (float4*)(out + (size_t)BB * DD + (size_t)b * SS);
        const int s4 = (part - 1) * 256 + tid;     // 0..511
        float4 sc = attn[s4];
        sc.x = __expf(sc.x - M) * invL;
        sc.y = __expf(sc.y - M) * invL;
        sc.z = __expf(sc.z - M) * invL;
        sc.w = __expf(sc.w - M) * invL;
        attn[s4] = sc;
    }
}

// ---------------------------------------------------------------------------
extern "C" void kernel_launch(void* const* d_in, const int* in_sizes, int n_in,
                              void* d_out, int out_size)
{
    const float* h       = (const float*)d_in[0];
    const float* context = (const float*)d_in[1];
    const int*   mask    = (const int*)d_in[2];
    float*       out     = (float*)d_out;

    dim3 gridA(NCHUNK, BB);
    attn_partial_kernel<<<gridA, THREADS>>>(h, context, mask, out + BB * DD);
    dim3 gridB(3, BB);
    attn_combine_kernel<<<gridB, 256>>>(out);
}